// round 2
// baseline (speedup 1.0000x reference)
#include <cuda_runtime.h>
#include <math.h>

// Problem constants (from reference)
#define Bv  8
#define Qv  1024
#define Sv  2048
#define Dv  1024
#define Hv  16
#define DH  64          // head dim
#define QT  16          // q rows per CTA
#define ST  256         // s tile (K/V staging)
#define NTH 256

// SMEM pitches (floats) chosen to kill bank conflicts
#define KP 65           // K/V tile pitch
#define QP 68           // Q tile pitch
#define SP 2049         // scores pitch

// SMEM float counts
#define SC_FLOATS   (QT * SP)          // 32784
#define K_FLOATS    (ST * KP)          // 16640
#define Q_FLOATS    (QT * QP)          // 1088
#define M_FLOATS    (Sv)               // 2048
#define R_FLOATS    (QT)               // 16
#define SMEM_FLOATS (SC_FLOATS + K_FLOATS + Q_FLOATS + M_FLOATS + R_FLOATS)

extern __shared__ float smem[];

__global__ void __launch_bounds__(NTH, 1)
attn_fused_kernel(const float* __restrict__ Qg,
                  const float* __restrict__ Kg,
                  const float* __restrict__ Vg,
                  const int*   __restrict__ Mg,
                  float* __restrict__ outg,
                  float* __restrict__ attng)
{
    float* sc   = smem;                 // [QT][SP]  raw scores -> unnormalized exp
    float* ksm  = sc  + SC_FLOATS;      // [ST][KP]  K tile, then V tile, then reduction buf
    float* qsm  = ksm + K_FLOATS;       // [QT][QP]  Q tile (pre-scaled by 1/8)
    float* mf   = qsm + Q_FLOATS;       // [Sv]      mask as float 0/1
    float* rinv = mf  + M_FLOATS;       // [QT]      1/rowsum

    const int q0  = blockIdx.x * QT;
    const int h   = blockIdx.y;
    const int b   = blockIdx.z;
    const int tid = threadIdx.x;

    const float* Qp = Qg + ((size_t)b * Qv + q0) * Dv + h * DH;
    const float* Kp = Kg + ((size_t)b * Sv) * Dv + h * DH;
    const float* Vp = Vg + ((size_t)b * Sv) * Dv + h * DH;

    // ---- phase 1: load Q tile (scaled by 1/sqrt(Dh)=1/8) and mask ----
    for (int i = tid; i < QT * DH; i += NTH) {
        int q = i >> 6, d = i & 63;
        qsm[q * QP + d] = Qp[(size_t)q * Dv + d] * 0.125f;
    }
    for (int s = tid; s < Sv; s += NTH)
        mf[s] = (float)Mg[(size_t)b * Sv + s];

    // ---- phase 2: scores[QT][S] = Qs @ K^T ----
    // thread -> 4q x 4s register tile over a 256-wide s stripe
    const int qg = tid & 3;     // q base = qg*4
    const int sg = tid >> 2;    // s base = sg*4 (covers 256)
    for (int st = 0; st < Sv; st += ST) {
        __syncthreads();
        for (int i = tid; i < ST * DH; i += NTH) {
            int r = i >> 6, d = i & 63;
            ksm[r * KP + d] = Kp[(size_t)(st + r) * Dv + d];
        }
        __syncthreads();

        float acc[4][4] = {};
        #pragma unroll 4
        for (int d = 0; d < DH; d++) {
            float kd[4], qd[4];
            #pragma unroll
            for (int j = 0; j < 4; j++) kd[j] = ksm[(sg * 4 + j) * KP + d];
            #pragma unroll
            for (int i = 0; i < 4; i++) qd[i] = qsm[(qg * 4 + i) * QP + d];
            #pragma unroll
            for (int i = 0; i < 4; i++)
                #pragma unroll
                for (int j = 0; j < 4; j++)
                    acc[i][j] += qd[i] * kd[j];
        }
        #pragma unroll
        for (int i = 0; i < 4; i++)
            #pragma unroll
            for (int j = 0; j < 4; j++)
                sc[(qg * 4 + i) * SP + st + sg * 4 + j] = acc[i][j];
    }
    __syncthreads();

    // ---- phase 3: masked softmax per row + write attention ----
    // Exact reduction of allennlp masked_softmax:
    //   attn_i = m_i*exp(s_i - M) / sum_{m_j=1} exp(s_j - M)   (TINY term ~2e-13 rel)
    const int warp = tid >> 5, lane = tid & 31;
    for (int q = warp; q < QT; q += (NTH / 32)) {
        float* row = sc + q * SP;
        float lmax = -1e30f;
        for (int s = lane; s < Sv; s += 32) {
            float v = row[s];
            if (mf[s] != 0.0f) lmax = fmaxf(lmax, v);
        }
        #pragma unroll
        for (int o = 16; o; o >>= 1)
            lmax = fmaxf(lmax, __shfl_xor_sync(0xffffffffu, lmax, o));

        float lsum = 0.0f;
        for (int s = lane; s < Sv; s += 32) {
            float e = (mf[s] != 0.0f) ? __expf(row[s] - lmax) : 0.0f;
            row[s] = e;          // keep unnormalized exp for PV
            lsum += e;
        }
        #pragma unroll
        for (int o = 16; o; o >>= 1)
            lsum += __shfl_xor_sync(0xffffffffu, lsum, o);

        float inv = 1.0f / (lsum + 1e-13f);
        if (lane == 0) rinv[q] = inv;

        float* ap = attng + (((size_t)b * Qv + q0 + q) * Hv + h) * Sv;
        for (int s = lane; s < Sv; s += 32)
            ap[s] = row[s] * inv;
    }
    __syncthreads();

    // ---- phase 4: out = (e @ V) * rinv ----
    // thread -> 8q x 2d accumulators, s split 4-ways across thread groups
    const int slice = tid >> 6;          // 0..3  (s-slice)
    const int qg2   = (tid >> 5) & 1;    // q base = qg2*8
    const int dg    = tid & 31;          // d in {dg, dg+32}
    float acc0[8], acc1[8];
    #pragma unroll
    for (int i = 0; i < 8; i++) { acc0[i] = 0.0f; acc1[i] = 0.0f; }

    for (int st = 0; st < Sv; st += ST) {
        __syncthreads();
        for (int i = tid; i < ST * DH; i += NTH) {
            int r = i >> 6, d = i & 63;
            ksm[r * KP + d] = Vp[(size_t)(st + r) * Dv + d];
        }
        __syncthreads();
        for (int sl = slice; sl < ST; sl += 4) {
            float v0 = ksm[sl * KP + dg];
            float v1 = ksm[sl * KP + dg + 32];
            const float* ep = sc + st + sl;
            #pragma unroll
            for (int i = 0; i < 8; i++) {
                float e = ep[(qg2 * 8 + i) * SP];   // broadcast within warp
                acc0[i] += e * v0;
                acc1[i] += e * v1;
            }
        }
    }

    // reduce the 4 s-slices via smem (reuse ksm)
    __syncthreads();
    float* red = ksm;   // needs 4*16*64 = 4096 floats <= K_FLOATS
    #pragma unroll
    for (int i = 0; i < 8; i++) {
        int q = qg2 * 8 + i;
        red[(slice * QT + q) * DH + dg]      = acc0[i];
        red[(slice * QT + q) * DH + dg + 32] = acc1[i];
    }
    __syncthreads();

    float* outp = outg + ((size_t)b * Qv + q0) * Dv + h * DH;
    for (int idx = tid; idx < QT * DH; idx += NTH) {
        int q = idx >> 6, d = idx & 63;
        float s = red[(0 * QT + q) * DH + d] + red[(1 * QT + q) * DH + d]
                + red[(2 * QT + q) * DH + d] + red[(3 * QT + q) * DH + d];
        outp[(size_t)q * Dv + d] = s * rinv[q];
    }
}

extern "C" void kernel_launch(void* const* d_in, const int* in_sizes, int n_in,
                              void* d_out, int out_size)
{
    const float* Qg = (const float*)d_in[0];
    const float* Kg = (const float*)d_in[1];
    const float* Vg = (const float*)d_in[2];
    const int*   Mg = (const int*)d_in[3];

    float* outg  = (float*)d_out;                       // [B,Q,D]
    float* attng = outg + (size_t)Bv * Qv * Dv;         // [B,Q,H,S]

    size_t smem_bytes = (size_t)SMEM_FLOATS * sizeof(float);  // 210304 B
    cudaFuncSetAttribute(attn_fused_kernel,
                         cudaFuncAttributeMaxDynamicSharedMemorySize,
                         (int)smem_bytes);

    dim3 grid(Qv / QT, Hv, Bv);   // (64, 16, 8)
    attn_fused_kernel<<<grid, NTH, smem_bytes>>>(Qg, Kg, Vg, Mg, outg, attng);
}

// round 5
// speedup vs baseline: 11.3998x; 11.3998x over previous
#include <cuda_runtime.h>
#include <cuda_bf16.h>
#include <cstdint>

// ---------------- problem constants ----------------
#define Bv 8
#define Qv 1024
#define Sv 2048
#define Dm 1024
#define Hv 16
#define DH 64
#define MT 128            // q rows per CTA
#define ST 64             // s per tile
#define NTILES (Sv / ST)  // 32
#define NTH 256

// bf16 tile pitch (elements / bytes)
#define PB  72
#define PBB (PB * 2)      // 144 B per row

// ---------------- smem layout (bytes) ----------------
#define SM_QHI   0
#define SM_QLO   (SM_QHI + MT * PBB)      // 18432
#define SM_KHI   (SM_QLO + MT * PBB)      // 36864
#define SM_KLO   (SM_KHI + ST * PBB)      // 46080
#define SM_VHI   (SM_KLO + ST * PBB)      // 55296
#define SM_VLO   (SM_VHI + ST * PBB)      // 64512
#define SM_MASK  (SM_VLO + ST * PBB)      // 73728  (2048 u8)
#define SM_STAGE (SM_MASK + 2048)         // 75776
#define STP 68                            // stage pitch (floats), 272B rows (16B aligned)
#define SMEM_TOTAL (SM_STAGE + MT * STP * 4)   // 110592

__device__ float g_rinv[Bv * Qv * Hv];

// ---------------- helpers ----------------
__device__ __forceinline__ uint32_t su32(const void* p) {
    uint32_t a;
    asm("{ .reg .u64 t; cvta.to.shared.u64 t, %1; cvt.u32.u64 %0, t; }" : "=r"(a) : "l"(p));
    return a;
}

__device__ __forceinline__ void ldm4(uint32_t* r, uint32_t a) {
    asm volatile("ldmatrix.sync.aligned.m8n8.x4.shared.b16 {%0,%1,%2,%3}, [%4];"
        : "=r"(r[0]), "=r"(r[1]), "=r"(r[2]), "=r"(r[3]) : "r"(a));
}
__device__ __forceinline__ void ldm4t(uint32_t* r, uint32_t a) {
    asm volatile("ldmatrix.sync.aligned.m8n8.x4.trans.shared.b16 {%0,%1,%2,%3}, [%4];"
        : "=r"(r[0]), "=r"(r[1]), "=r"(r[2]), "=r"(r[3]) : "r"(a));
}
__device__ __forceinline__ void mma16816(float* d, const uint32_t* a, uint32_t b0, uint32_t b1) {
    asm volatile("mma.sync.aligned.m16n8k16.row.col.f32.bf16.bf16.f32 "
        "{%0,%1,%2,%3}, {%4,%5,%6,%7}, {%8,%9}, {%0,%1,%2,%3};"
        : "+f"(d[0]), "+f"(d[1]), "+f"(d[2]), "+f"(d[3])
        : "r"(a[0]), "r"(a[1]), "r"(a[2]), "r"(a[3]), "r"(b0), "r"(b1));
}

// pack two fp32 into bf16x2 hi + bf16x2 lo (split)
__device__ __forceinline__ void pack2(float e0, float e1, uint32_t& hi, uint32_t& lo) {
    __nv_bfloat162 h = __floats2bfloat162_rn(e0, e1);
    hi = *(uint32_t*)&h;
    float f0 = __bfloat162float(__low2bfloat16(h));
    float f1 = __bfloat162float(__high2bfloat16(h));
    __nv_bfloat162 l = __floats2bfloat162_rn(e0 - f0, e1 - f1);
    lo = *(uint32_t*)&l;
}

// split a float2 into hi/lo bf16x2 tiles at (row, dpair)
__device__ __forceinline__ void split_store(char* hib, char* lob, int row, int dp, float2 v) {
    uint32_t h, l;
    pack2(v.x, v.y, h, l);
    *(uint32_t*)(hib + row * PBB + dp * 4) = h;
    *(uint32_t*)(lob + row * PBB + dp * 4) = l;
}

// ======================= K1: fused attention =======================
extern __shared__ char smem[];

__global__ void __launch_bounds__(NTH, 2)
attn_k1(const float* __restrict__ Qg, const float* __restrict__ Kg,
        const float* __restrict__ Vg, const int* __restrict__ Mg,
        float* __restrict__ outg, float* __restrict__ attng)
{
    const int tid  = threadIdx.x;
    const int lane = tid & 31;
    const int wq   = tid >> 5;          // warp -> q rows [wq*16, wq*16+16)
    const int q0   = blockIdx.x * MT;
    const int h    = blockIdx.y;
    const int b    = blockIdx.z;

    const uint32_t sb = su32(smem);
    unsigned char* mk = (unsigned char*)(smem + SM_MASK);
    float* stg = (float*)(smem + SM_STAGE);

    // ---- prologue: Q (scaled by 1/8, hi/lo split) + mask ----
    #pragma unroll 4
    for (int it = 0; it < 16; it++) {
        int idx = tid + it * NTH;
        int m = idx >> 5, dp = idx & 31;
        float2 v = *(const float2*)(Qg + ((size_t)(b * Qv + q0 + m)) * Dm + h * DH + dp * 2);
        v.x *= 0.125f; v.y *= 0.125f;
        split_store(smem + SM_QHI, smem + SM_QLO, m, dp, v);
    }
    for (int s = tid; s < Sv; s += NTH)
        mk[s] = (unsigned char)Mg[(size_t)b * Sv + s];

    const float* Kp = Kg + (size_t)b * Sv * Dm + h * DH;
    const float* Vp = Vg + (size_t)b * Sv * Dm + h * DH;

    // ---- per-thread ldmatrix addresses ----
    // A (Q / row-major 16x16): m0 rows0-7, m1 rows8-15, m2 rows0-7(+16B), m3 rows8-15(+16B)
    const uint32_t aAoff = (uint32_t)((wq * 16 + (lane & 15)) * PBB + ((lane & 16) >> 4) * 16);
    const uint32_t aAhi = sb + SM_QHI + aAoff;
    const uint32_t aAlo = sb + SM_QLO + aAoff;
    // B for QK^T (K rows = n, non-trans): m0 n0-7 k0-7, m1 n0-7 k8-15, m2 n8-15 k0-7, m3 n8-15 k8-15
    const uint32_t aBoff = (uint32_t)(((lane & 7) + ((lane & 16) >> 1)) * PBB + ((lane & 8) << 1));
    // B for PV (V rows = k, trans): m0 k0-7 d0-7, m1 k8-15 d0-7, m2 k0-7 d8-15, m3 k8-15 d8-15
    const uint32_t aVoff = (uint32_t)(((lane & 7) + (lane & 8)) * PBB + ((lane >> 4) & 1) * 16);

    const int r = lane >> 2, c = lane & 3;

    float O[8][4];
    #pragma unroll
    for (int nt = 0; nt < 8; nt++)
        #pragma unroll
        for (int j = 0; j < 4; j++) O[nt][j] = 0.0f;
    float rsl = 0.0f, rsh = 0.0f;

    for (int i = 0; i < NTILES; i++) {
        __syncthreads();     // previous iter's MMA2 done reading V
        // ---- load K(i), V(i) hi/lo ----
        #pragma unroll 4
        for (int it = 0; it < 8; it++) {
            int idx = tid + it * NTH;
            int rr = idx >> 5, dp = idx & 31;
            float2 kv = *(const float2*)(Kp + (size_t)(i * ST + rr) * Dm + dp * 2);
            split_store(smem + SM_KHI, smem + SM_KLO, rr, dp, kv);
            float2 vv = *(const float2*)(Vp + (size_t)(i * ST + rr) * Dm + dp * 2);
            split_store(smem + SM_VHI, smem + SM_VLO, rr, dp, vv);
        }
        __syncthreads();

        // ---- MMA1: S = Qs @ K^T (hi*hi + hi*lo + lo*hi) ----
        float S[8][4];
        #pragma unroll
        for (int nt = 0; nt < 8; nt++)
            #pragma unroll
            for (int j = 0; j < 4; j++) S[nt][j] = 0.0f;

        #pragma unroll
        for (int k4 = 0; k4 < 4; k4++) {
            uint32_t ah[4], al[4];
            ldm4(ah, aAhi + k4 * 32);
            ldm4(al, aAlo + k4 * 32);
            #pragma unroll
            for (int np = 0; np < 4; np++) {
                uint32_t bo = aBoff + np * 16 * PBB + k4 * 32;
                uint32_t bh[4], bl[4];
                ldm4(bh, sb + SM_KHI + bo);
                ldm4(bl, sb + SM_KLO + bo);
                mma16816(S[2*np],   ah, bh[0], bh[1]);
                mma16816(S[2*np+1], ah, bh[2], bh[3]);
                mma16816(S[2*np],   ah, bl[0], bl[1]);
                mma16816(S[2*np+1], ah, bl[2], bl[3]);
                mma16816(S[2*np],   al, bh[0], bh[1]);
                mma16816(S[2*np+1], al, bh[2], bh[3]);
            }
        }

        // ---- mask * exp, rowsum, stage (unnormalized) ----
        const int s0 = i * ST;
        #pragma unroll
        for (int nt = 0; nt < 8; nt++) {
            int col = nt * 8 + 2 * c;
            float m0 = (float)mk[s0 + col], m1 = (float)mk[s0 + col + 1];
            float e0 = m0 * __expf(S[nt][0]);
            float e1 = m1 * __expf(S[nt][1]);
            float e2 = m0 * __expf(S[nt][2]);
            float e3 = m1 * __expf(S[nt][3]);
            rsl += e0 + e1; rsh += e2 + e3;
            S[nt][0] = e0; S[nt][1] = e1; S[nt][2] = e2; S[nt][3] = e3;
            *(float2*)&stg[(wq * 16 + r)     * STP + col] = make_float2(e0, e1);
            *(float2*)&stg[(wq * 16 + r + 8) * STP + col] = make_float2(e2, e3);
        }

        // ---- MMA2: O += P @ V (Phi*Vhi + Phi*Vlo + Plo*Vhi), P from registers ----
        #pragma unroll
        for (int kt = 0; kt < 4; kt++) {
            uint32_t ph[4], pl[4];
            pack2(S[2*kt][0],   S[2*kt][1],   ph[0], pl[0]);
            pack2(S[2*kt][2],   S[2*kt][3],   ph[1], pl[1]);
            pack2(S[2*kt+1][0], S[2*kt+1][1], ph[2], pl[2]);
            pack2(S[2*kt+1][2], S[2*kt+1][3], ph[3], pl[3]);
            #pragma unroll
            for (int np = 0; np < 4; np++) {
                uint32_t bo = aVoff + kt * 16 * PBB + np * 32;
                uint32_t vh4[4], vl4[4];
                ldm4t(vh4, sb + SM_VHI + bo);
                ldm4t(vl4, sb + SM_VLO + bo);
                mma16816(O[2*np],   ph, vh4[0], vh4[1]);
                mma16816(O[2*np+1], ph, vh4[2], vh4[3]);
                mma16816(O[2*np],   ph, vl4[0], vl4[1]);
                mma16816(O[2*np+1], ph, vl4[2], vl4[3]);
                mma16816(O[2*np],   pl, vh4[0], vh4[1]);
                mma16816(O[2*np+1], pl, vh4[2], vh4[3]);
            }
        }

        // ---- coalesced attention write (unnormalized e) ----
        __syncwarp();
        #pragma unroll
        for (int it = 0; it < 8; it++) {
            int row2 = it * 2 + (lane >> 4);       // 0..15
            int c4   = lane & 15;                  // float4 col
            float4 v = *(float4*)&stg[(wq * 16 + row2) * STP + c4 * 4];
            *(float4*)(attng + (((size_t)(b * Qv + q0 + wq * 16 + row2)) * Hv + h) * Sv
                       + s0 + c4 * 4) = v;
        }
    }

    // ---- final: rowsum reduce, rinv, normalize O, write out ----
    rsl += __shfl_xor_sync(0xffffffffu, rsl, 1);
    rsl += __shfl_xor_sync(0xffffffffu, rsl, 2);
    rsh += __shfl_xor_sync(0xffffffffu, rsh, 1);
    rsh += __shfl_xor_sync(0xffffffffu, rsh, 2);
    const float il = 1.0f / (rsl + 1e-13f);
    const float ih = 1.0f / (rsh + 1e-13f);

    if (c == 0) {
        g_rinv[(size_t)(b * Qv + q0 + wq * 16 + r)     * Hv + h] = il;
        g_rinv[(size_t)(b * Qv + q0 + wq * 16 + r + 8) * Hv + h] = ih;
    }

    float* orow0 = outg + (size_t)(b * Qv + q0 + wq * 16 + r)     * Dm + h * DH;
    float* orow1 = outg + (size_t)(b * Qv + q0 + wq * 16 + r + 8) * Dm + h * DH;
    #pragma unroll
    for (int nt = 0; nt < 8; nt++) {
        int col = nt * 8 + 2 * c;
        *(float2*)(orow0 + col) = make_float2(O[nt][0] * il, O[nt][1] * il);
        *(float2*)(orow1 + col) = make_float2(O[nt][2] * ih, O[nt][3] * ih);
    }
}

// ======================= K3: rescale attention =======================
__global__ void __launch_bounds__(256)
rescale_k3(float* __restrict__ attn)
{
    size_t i4 = (size_t)blockIdx.x * 256 + threadIdx.x;   // float4 index
    float rinv = g_rinv[i4 >> 9];                         // 512 float4 per (b,q,h) row
    float4* p = (float4*)attn + i4;
    float4 v = *p;
    v.x *= rinv; v.y *= rinv; v.z *= rinv; v.w *= rinv;
    *p = v;
}

// ======================= launch =======================
extern "C" void kernel_launch(void* const* d_in, const int* in_sizes, int n_in,
                              void* d_out, int out_size)
{
    const float* Qg = (const float*)d_in[0];
    const float* Kg = (const float*)d_in[1];
    const float* Vg = (const float*)d_in[2];
    const int*   Mg = (const int*)d_in[3];

    float* outg  = (float*)d_out;                     // [B,Q,D]
    float* attng = outg + (size_t)Bv * Qv * Dm;       // [B,Q,H,S]

    cudaFuncSetAttribute(attn_k1, cudaFuncAttributeMaxDynamicSharedMemorySize, SMEM_TOTAL);

    dim3 grid(Qv / MT, Hv, Bv);                       // (8,16,8) = 1024 CTAs
    attn_k1<<<grid, NTH, SMEM_TOTAL>>>(Qg, Kg, Vg, Mg, outg, attng);

    size_t n4 = (size_t)Bv * Qv * Hv * Sv / 4;        // 67,108,864 float4
    rescale_k3<<<(unsigned)(n4 / 256), 256>>>(attng);
}